// round 3
// baseline (speedup 1.0000x reference)
#include <cuda_runtime.h>

// Problem constants
#define G_    8
#define FG_   16
#define J_    8
#define W_    31
#define PAD1_ 15
#define L_    262144
#define TL_   512         // k positions per CTA
#define KT_   4           // k positions per thread
#define NTHREADS_ 256

#define HALF_ELEMS_ (4 * J_ * W_ * FG_)   // 15872 floats = 62 KB per half

// Constant bank holds ONE half (4 groups), layout [g4][j][w][f]
// so filter pairs are adjacent 8B-aligned 64-bit words.
__constant__ float c_w[HALF_ELEMS_];

// Staging buffer for the transposed weights (both halves).
__device__ float d_wt[2 * HALF_ELEMS_];

typedef unsigned long long ull;

__device__ __forceinline__ ull ffma2(ull a, ull b, ull c) {
    ull d;
    asm("fma.rn.f32x2 %0, %1, %2, %3;" : "=l"(d) : "l"(a), "l"(b), "l"(c));
    return d;
}
__device__ __forceinline__ ull dup2(float x) {
    ull d;
    asm("mov.b64 %0, {%1, %1};" : "=l"(d) : "f"(x));
    return d;
}
__device__ __forceinline__ void unpack2(ull v, float& lo, float& hi) {
    asm("mov.b64 {%0, %1}, %2;" : "=f"(lo), "=f"(hi) : "l"(v));
}

// Transpose params [g][f][j][w] -> d_wt [h][g4][j][w][f]
__global__ void transpose_w(const float* __restrict__ p) {
    int idx = blockIdx.x * blockDim.x + threadIdx.x;
    if (idx >= 2 * HALF_ELEMS_) return;
    int f = idx & 15;
    int t = idx >> 4;
    int w = t % W_;  t /= W_;
    int j = t & 7;   t >>= 3;
    int g = t;                       // 0..7 (h*4+g4)
    d_wt[idx] = p[((g * FG_ + f) * J_ + j) * W_ + w];
}

// One half: 4 groups. y[g,f,k] = sum_{j,w} x[rel[g,j], k-15+w] * K[g,f,j,w]
// Thread: 8 filters (4 f32x2 pairs, filter-packed) x 4 consecutive k.
__global__ void __launch_bounds__(NTHREADS_)
conv_half(const float* __restrict__ x,
          const int* __restrict__ rel,
          float* __restrict__ out,
          int g_base)
{
    const int gl   = blockIdx.y;          // 0..3
    const int g    = g_base + gl;
    const int tile = blockIdx.x;
    const int tid  = threadIdx.x;

    const int fb   = tid >> 7;            // 0..1 : filters [fb*8, fb*8+8)
    const int kidx = tid & 127;
    const int kb   = tile * TL_ + kidx * KT_;

    ull acc[4][KT_];
#pragma unroll
    for (int p = 0; p < 4; ++p)
#pragma unroll
        for (int t = 0; t < KT_; ++t) acc[p][t] = 0ull;

    int rows[J_];
#pragma unroll
    for (int j = 0; j < J_; ++j) rows[j] = __ldg(rel + g * J_ + j);

    // window covers x[kb-16 .. kb+19] (36 floats, 16B-aligned base)
    const bool safe = (kb >= 16) && (kb + 20 <= L_);

#pragma unroll 1
    for (int j = 0; j < J_; ++j) {
        const float* xr = x + rows[j] * L_;

        float xw[36];
        if (safe) {
            const float4* xp4 = (const float4*)(xr + kb - 16);
#pragma unroll
            for (int q = 0; q < 9; ++q) {
                float4 v = __ldg(xp4 + q);
                xw[4 * q + 0] = v.x; xw[4 * q + 1] = v.y;
                xw[4 * q + 2] = v.z; xw[4 * q + 3] = v.w;
            }
        } else {
            // clamped loads pollute only edge outputs, overwritten below
#pragma unroll
            for (int i = 0; i < 36; ++i) {
                int ix = kb - 16 + i;
                ix = max(0, min(L_ - 1, ix));
                xw[i] = __ldg(xr + ix);
            }
        }

        // weights: warp-uniform 64-bit loads from constant -> LDCU/UR expected
        const float* cwj = c_w + (gl * J_ + j) * (W_ * FG_) + fb * 8;
#pragma unroll
        for (int w = 0; w < W_; ++w) {
            const ull* wq = (const ull*)(cwj + w * FG_);
            ull w0 = wq[0];
            ull w1 = wq[1];
            ull w2 = wq[2];
            ull w3 = wq[3];
#pragma unroll
            for (int t = 0; t < KT_; ++t) {
                ull xd = dup2(xw[w + t + 1]);
                acc[0][t] = ffma2(xd, w0, acc[0][t]);
                acc[1][t] = ffma2(xd, w1, acc[1][t]);
                acc[2][t] = ffma2(xd, w2, acc[2][t]);
                acc[3][t] = ffma2(xd, w3, acc[3][t]);
            }
        }
    }

    // Store: per filter, 4 consecutive k -> float4 (kb 16B-aligned)
#pragma unroll
    for (int p = 0; p < 4; ++p) {
        float a0[KT_], a1[KT_];
#pragma unroll
        for (int t = 0; t < KT_; ++t) unpack2(acc[p][t], a0[t], a1[t]);
        const int f0 = fb * 8 + 2 * p;
        *(float4*)(out + (g * FG_ + f0) * L_ + kb) =
            make_float4(a0[0], a0[1], a0[2], a0[3]);
        *(float4*)(out + (g * FG_ + f0 + 1) * L_ + kb) =
            make_float4(a1[0], a1[1], a1[2], a1[3]);
    }

    // ---- Boundary overwrite (reference truncates; it does NOT zero-pad) ----
    //  left  k in [0,15):  y[k] = sum_j sum_{w<=k+15} x[row, w]      * K[j,w]
    //  right k=L-15+e:     y[k] = sum_j sum_{w>=e+1}  x[row, L-31+w] * K[j,w]
    if (tile == 0 || tile == (L_ / TL_ - 1)) {
        __syncthreads();   // order after interior stores
        if (tid < FG_ * PAD1_) {
            const int f = tid / PAD1_;      // 0..15
            const int e = tid % PAD1_;      // 0..14
            float s = 0.f;
            if (tile == 0) {
                for (int j = 0; j < J_; ++j) {
                    const float* xr = x + rows[j] * L_;
                    for (int w = 0; w <= e + PAD1_; ++w)
                        s += xr[w] * c_w[((gl * J_ + j) * W_ + w) * FG_ + f];
                }
                out[(g * FG_ + f) * L_ + e] = s;
            } else {
                for (int j = 0; j < J_; ++j) {
                    const float* xr = x + rows[j] * L_;
                    for (int w = e + 1; w < W_; ++w)
                        s += xr[L_ - W_ + w] * c_w[((gl * J_ + j) * W_ + w) * FG_ + f];
                }
                out[(g * FG_ + f) * L_ + (L_ - PAD1_ + e)] = s;
            }
        }
    }
}

extern "C" void kernel_launch(void* const* d_in, const int* in_sizes, int n_in,
                              void* d_out, int out_size)
{
    const float* x      = (const float*)d_in[0];
    const float* params = (const float*)d_in[1];
    const int*   rel    = (const int*)d_in[2];
    float* out = (float*)d_out;

    // 1) transpose weights into staging buffer
    transpose_w<<<(2 * HALF_ELEMS_ + 255) / 256, 256>>>(params);

    void* wt_ptr = nullptr;
    cudaGetSymbolAddress(&wt_ptr, d_wt);
    const float* wt = (const float*)wt_ptr;

    dim3 grid(L_ / TL_, 4);   // 512 x 4 = 2048 CTAs per half

    // 2) half 0: groups 0-3
    cudaMemcpyToSymbolAsync(c_w, wt, HALF_ELEMS_ * sizeof(float), 0,
                            cudaMemcpyDeviceToDevice, 0);
    conv_half<<<grid, NTHREADS_>>>(x, rel, out, 0);

    // 3) half 1: groups 4-7
    cudaMemcpyToSymbolAsync(c_w, wt + HALF_ELEMS_, HALF_ELEMS_ * sizeof(float), 0,
                            cudaMemcpyDeviceToDevice, 0);
    conv_half<<<grid, NTHREADS_>>>(x, rel, out, 4);
}

// round 5
// speedup vs baseline: 2.1588x; 2.1588x over previous
#include <cuda_runtime.h>
#include <cstdint>

#define G_    8
#define FG_   16
#define J_    8
#define W_    31
#define PAD1_ 15
#define L_    262144
#define KTILE_ 512
#define NTH_  256

// SMEM layout (uint32/float elements)
#define XS_PITCH 544                     // per-j x window row (tf32 bits)
#define XS_ELEMS (J_ * XS_PITCH)         // 4352
#define WS_ELEMS (J_ * 32 * FG_)         // 4096  [j][w(32, padded)][f]
#define YT_PITCH 516                     // conflict-free: bank = 8*tig+gid
#define YT_ELEMS (FG_ * YT_PITCH)        // 8256
#define SM_XS 0
#define SM_WS (SM_XS + XS_ELEMS)
#define SM_YT (SM_WS + WS_ELEMS)
#define SMEM_WORDS (SM_YT + YT_ELEMS)    // 16704 words = 66816 B

__device__ __forceinline__ uint32_t cvt_tf32(float f) {
    uint32_t r;
    asm("cvt.rna.tf32.f32 %0, %1;" : "=r"(r) : "f"(f));
    return r;
}

__device__ __forceinline__ void mma_tf32(float d[4],
                                         uint32_t a0, uint32_t a1,
                                         uint32_t a2, uint32_t a3,
                                         uint32_t b0, uint32_t b1) {
    asm volatile(
        "mma.sync.aligned.m16n8k8.row.col.f32.tf32.tf32.f32 "
        "{%0,%1,%2,%3}, {%4,%5,%6,%7}, {%8,%9}, {%0,%1,%2,%3};"
        : "+f"(d[0]), "+f"(d[1]), "+f"(d[2]), "+f"(d[3])
        : "r"(a0), "r"(a1), "r"(a2), "r"(a3), "r"(b0), "r"(b1));
}

// CTA: one group g, 512 consecutive k, all 16 filters.
// Warp: 64 k (4 m16-tiles) x 16 f (2 n8-halves), reduction over 32 (j,w-octet) chunks.
// A[m,kk] = xs[j][m + w0 + kk]  -- Toeplitz aliasing, no im2col duplication.
__global__ void __launch_bounds__(NTH_)
conv_mma(const float* __restrict__ x,
         const float* __restrict__ params,
         const int* __restrict__ rel,
         float* __restrict__ out)
{
    extern __shared__ uint32_t sm[];
    const int tid  = threadIdx.x;
    const int wid  = tid >> 5;
    const int lane = tid & 31;
    const int gid  = lane >> 2;     // groupID 0..7
    const int tig  = lane & 3;      // thread-in-group 0..3
    const int g    = blockIdx.y;
    const int tile = blockIdx.x;
    const int kb   = tile * KTILE_;

    int rows[J_];
#pragma unroll
    for (int j = 0; j < J_; ++j) rows[j] = __ldg(rel + g * J_ + j);

    // ---- stage x windows: xs[j][t] = tf32(x[row_j][clamp(kb + t - 15)]) ----
    // clamp pollutes only k<15 / k>=L-15 outputs, overwritten at the end.
    for (int e = tid; e < XS_ELEMS; e += NTH_) {
        int t = e % XS_PITCH;
        int j = e / XS_PITCH;
        int gi = kb + t - PAD1_;
        gi = max(0, min(L_ - 1, gi));
        sm[SM_XS + j * XS_PITCH + t] = cvt_tf32(__ldg(x + rows[j] * L_ + gi));
    }
    // ---- stage weights transposed: ws[j][w][f], w padded 31->32 with zeros ----
    for (int e = tid; e < WS_ELEMS; e += NTH_) {
        int f = e & 15;
        int w = (e >> 4) & 31;
        int j = e >> 9;
        float v = (w < W_) ? __ldg(params + ((g * FG_ + f) * J_ + j) * W_ + w) : 0.f;
        sm[SM_WS + e] = cvt_tf32(v);
    }
    __syncthreads();

    const int warpk = wid * 64;     // this warp's k offset in the tile

    float acc[4][2][4];
#pragma unroll
    for (int mi = 0; mi < 4; ++mi)
#pragma unroll
        for (int nh = 0; nh < 2; ++nh)
#pragma unroll
            for (int q = 0; q < 4; ++q) acc[mi][nh][q] = 0.f;

#pragma unroll 1
    for (int j = 0; j < J_; ++j) {
        const uint32_t* xj = sm + SM_XS + j * XS_PITCH;
        const uint32_t* wj = sm + SM_WS + j * (32 * FG_);
#pragma unroll
        for (int w0g = 0; w0g < 4; ++w0g) {
            // B fragments: b[kk,n] = ws[j][w0+kk][n]
            uint32_t b0a = wj[(w0g * 8 + tig) * FG_ + gid];
            uint32_t b1a = wj[(w0g * 8 + tig + 4) * FG_ + gid];
            uint32_t b0b = wj[(w0g * 8 + tig) * FG_ + 8 + gid];
            uint32_t b1b = wj[(w0g * 8 + tig + 4) * FG_ + 8 + gid];
#pragma unroll
            for (int mi = 0; mi < 4; ++mi) {
                const uint32_t* ab = xj + warpk + mi * 16 + w0g * 8;
                uint32_t a0 = ab[gid + tig];
                uint32_t a1 = ab[gid + 8 + tig];
                uint32_t a2 = ab[gid + tig + 4];
                uint32_t a3 = ab[gid + 8 + tig + 4];
                mma_tf32(acc[mi][0], a0, a1, a2, a3, b0a, b1a);
                mma_tf32(acc[mi][1], a0, a1, a2, a3, b0b, b1b);
            }
        }
    }

    // ---- D fragments -> yt[f][k] (pitch 516: perfectly conflict-free) ----
    float* yt = (float*)(sm + SM_YT);
#pragma unroll
    for (int mi = 0; mi < 4; ++mi) {
        const int k0 = warpk + mi * 16 + gid;
#pragma unroll
        for (int nh = 0; nh < 2; ++nh) {
            const int f0 = nh * 8 + 2 * tig;
            yt[f0 * YT_PITCH + k0]           = acc[mi][nh][0];
            yt[(f0 + 1) * YT_PITCH + k0]     = acc[mi][nh][1];
            yt[f0 * YT_PITCH + k0 + 8]       = acc[mi][nh][2];
            yt[(f0 + 1) * YT_PITCH + k0 + 8] = acc[mi][nh][3];
        }
    }
    __syncthreads();

    // ---- coalesced float4 store ----
    for (int i = tid; i < FG_ * (KTILE_ / 4); i += NTH_) {
        int f  = i >> 7;
        int c4 = i & 127;
        float4 v = *(const float4*)(yt + f * YT_PITCH + c4 * 4);
        *(float4*)(out + (g * FG_ + f) * L_ + kb + c4 * 4) = v;
    }

    // ---- boundary overwrite (reference truncates; no zero-pad), full fp32 ----
    if (tile == 0 || tile == (L_ / KTILE_ - 1)) {
        __syncthreads();
        if (tid < FG_ * PAD1_) {
            const int f = tid / PAD1_;
            const int e = tid % PAD1_;
            const float* pk = params + (g * FG_ + f) * (J_ * W_);
            float s = 0.f;
            if (tile == 0) {
                for (int j = 0; j < J_; ++j) {
                    const float* xr = x + rows[j] * L_;
                    for (int w = 0; w <= e + PAD1_; ++w)
                        s += xr[w] * pk[j * W_ + w];
                }
                out[(g * FG_ + f) * L_ + e] = s;
            } else {
                for (int j = 0; j < J_; ++j) {
                    const float* xr = x + rows[j] * L_;
                    for (int w = e + 1; w < W_; ++w)
                        s += xr[L_ - W_ + w] * pk[j * W_ + w];
                }
                out[(g * FG_ + f) * L_ + (L_ - PAD1_ + e)] = s;
            }
        }
    }
}

extern "C" void kernel_launch(void* const* d_in, const int* in_sizes, int n_in,
                              void* d_out, int out_size)
{
    const float* x      = (const float*)d_in[0];
    const float* params = (const float*)d_in[1];
    const int*   rel    = (const int*)d_in[2];
    float* out = (float*)d_out;

    cudaFuncSetAttribute(conv_mma, cudaFuncAttributeMaxDynamicSharedMemorySize,
                         SMEM_WORDS * 4);
    dim3 grid(L_ / KTILE_, G_);   // 512 x 8
    conv_mma<<<grid, NTH_, SMEM_WORDS * 4>>>(x, params, rel, out);
}

// round 6
// speedup vs baseline: 2.2603x; 1.0470x over previous
#include <cuda_runtime.h>
#include <cstdint>

#define G_    8
#define FG_   16
#define J_    8
#define W_    31
#define PAD1_ 15
#define L_    262144
#define KTILE_ 512
#define NTH_  256

// SMEM layout (32-bit words). yt ALIASES xs+ws (dead after main loop).
#define XS_PITCH 544                     // 512 + 31, rounded to 16B
#define XS_ELEMS (J_ * XS_PITCH)         // 4352
#define WSP      24                      // ws pitch: conflict-free B loads
#define WS_ELEMS (J_ * 32 * WSP)         // 6144
#define YT_PITCH 516                     // fragment writes conflict-free (P%16==4)
#define YT_ELEMS (FG_ * YT_PITCH)        // 8256
#define SM_XS 0
#define SM_WS (SM_XS + XS_ELEMS)         // 4352
#define SM_YT 0                          // aliases xs/ws
#define SMEM_WORDS (SM_WS + WS_ELEMS)    // 10496 words = 41984 B -> 5 CTAs/SM

__device__ __forceinline__ uint32_t cvt_tf32(float f) {
    uint32_t r;
    asm("cvt.rna.tf32.f32 %0, %1;" : "=r"(r) : "f"(f));
    return r;
}

__device__ __forceinline__ void mma_tf32(float d[4],
                                         uint32_t a0, uint32_t a1,
                                         uint32_t a2, uint32_t a3,
                                         uint32_t b0, uint32_t b1) {
    asm volatile(
        "mma.sync.aligned.m16n8k8.row.col.f32.tf32.tf32.f32 "
        "{%0,%1,%2,%3}, {%4,%5,%6,%7}, {%8,%9}, {%0,%1,%2,%3};"
        : "+f"(d[0]), "+f"(d[1]), "+f"(d[2]), "+f"(d[3])
        : "r"(a0), "r"(a1), "r"(a2), "r"(a3), "r"(b0), "r"(b1));
}

// CTA: one group g, 512 consecutive k, 16 filters.
// Warp: 64 k (4 m16-tiles) x 16 f. A[m,kk] = xs[j][m + w0 + kk] (Toeplitz alias).
// Sliding A-fragments across w-octets: a0' = a1, a2' = a3.
__global__ void __launch_bounds__(NTH_)
conv_mma(const float* __restrict__ x,
         const float* __restrict__ params,
         const int* __restrict__ rel,
         float* __restrict__ out)
{
    extern __shared__ uint32_t sm[];
    const int tid  = threadIdx.x;
    const int wid  = tid >> 5;
    const int lane = tid & 31;
    const int gid  = lane >> 2;
    const int tig  = lane & 3;
    const int g    = blockIdx.y;
    const int tile = blockIdx.x;
    const int kb   = tile * KTILE_;

    int rows[J_];
#pragma unroll
    for (int j = 0; j < J_; ++j) rows[j] = __ldg(rel + g * J_ + j);

    // ---- stage x windows: xs[j][t] = tf32(x[row_j][clamp(kb + t - 15)]) ----
    for (int e = tid; e < XS_ELEMS; e += NTH_) {
        int t = e % XS_PITCH;
        int j = e / XS_PITCH;
        int gi = kb + t - PAD1_;
        gi = max(0, min(L_ - 1, gi));
        sm[SM_XS + j * XS_PITCH + t] = cvt_tf32(__ldg(x + rows[j] * L_ + gi));
    }
    // ---- stage weights: ws[j][w][f] with pitch 24, w padded 31->32 ----
    for (int e = tid; e < J_ * 32 * FG_; e += NTH_) {
        int f = e & 15;
        int w = (e >> 4) & 31;
        int j = e >> 9;
        float v = (w < W_) ? __ldg(params + ((g * FG_ + f) * J_ + j) * W_ + w) : 0.f;
        sm[SM_WS + (j * 32 + w) * WSP + f] = cvt_tf32(v);
    }
    __syncthreads();

    const int warpk = wid * 64;

    float acc[4][2][4];
#pragma unroll
    for (int mi = 0; mi < 4; ++mi)
#pragma unroll
        for (int nh = 0; nh < 2; ++nh)
#pragma unroll
            for (int q = 0; q < 4; ++q) acc[mi][nh][q] = 0.f;

#pragma unroll 1
    for (int j = 0; j < J_; ++j) {
        const uint32_t* xj = sm + SM_XS + j * XS_PITCH + warpk + gid + tig;
        const uint32_t* wj = sm + SM_WS + j * (32 * WSP);

        // init A fragments for w0g = 0
        uint32_t A[4][4];
#pragma unroll
        for (int mi = 0; mi < 4; ++mi) {
            A[mi][0] = xj[mi * 16];
            A[mi][1] = xj[mi * 16 + 8];
            A[mi][2] = xj[mi * 16 + 4];
            A[mi][3] = xj[mi * 16 + 12];
        }

#pragma unroll
        for (int w0g = 0; w0g < 4; ++w0g) {
            const uint32_t* wb = wj + (w0g * 8 + tig) * WSP + gid;
            uint32_t b0a = wb[0];
            uint32_t b1a = wb[4 * WSP];
            uint32_t b0b = wb[8];
            uint32_t b1b = wb[4 * WSP + 8];
#pragma unroll
            for (int mi = 0; mi < 4; ++mi) {
                mma_tf32(acc[mi][0], A[mi][0], A[mi][1], A[mi][2], A[mi][3], b0a, b1a);
                mma_tf32(acc[mi][1], A[mi][0], A[mi][1], A[mi][2], A[mi][3], b0b, b1b);
            }
            if (w0g < 3) {
                // slide: a0' = a1, a2' = a3; two fresh loads per m-tile
#pragma unroll
                for (int mi = 0; mi < 4; ++mi) {
                    A[mi][0] = A[mi][1];
                    A[mi][2] = A[mi][3];
                    A[mi][1] = xj[mi * 16 + (w0g + 1) * 8 + 8];
                    A[mi][3] = xj[mi * 16 + (w0g + 1) * 8 + 12];
                }
            }
        }
    }

    __syncthreads();   // xs/ws dead; yt aliases them

    // ---- D fragments -> yt[f][k], conflict-free (pitch 516) ----
    float* yt = (float*)(sm + SM_YT);
#pragma unroll
    for (int mi = 0; mi < 4; ++mi) {
        const int k0 = warpk + mi * 16 + gid;
#pragma unroll
        for (int nh = 0; nh < 2; ++nh) {
            const int f0 = nh * 8 + 2 * tig;
            yt[f0 * YT_PITCH + k0]           = acc[mi][nh][0];
            yt[(f0 + 1) * YT_PITCH + k0]     = acc[mi][nh][1];
            yt[f0 * YT_PITCH + k0 + 8]       = acc[mi][nh][2];
            yt[(f0 + 1) * YT_PITCH + k0 + 8] = acc[mi][nh][3];
        }
    }
    __syncthreads();

    // ---- coalesced float4 store ----
    for (int i = tid; i < FG_ * (KTILE_ / 4); i += NTH_) {
        int f  = i >> 7;
        int c4 = i & 127;
        float4 v = *(const float4*)(yt + f * YT_PITCH + c4 * 4);
        *(float4*)(out + (g * FG_ + f) * L_ + kb + c4 * 4) = v;
    }

    // ---- boundary overwrite (reference truncates; no zero-pad), full fp32 ----
    if (tile == 0 || tile == (L_ / KTILE_ - 1)) {
        __syncthreads();
        if (tid < FG_ * PAD1_) {
            const int f = tid / PAD1_;
            const int e = tid % PAD1_;
            const float* pk = params + (g * FG_ + f) * (J_ * W_);
            float s = 0.f;
            if (tile == 0) {
                for (int j = 0; j < J_; ++j) {
                    const float* xr = x + rows[j] * L_;
                    for (int w = 0; w <= e + PAD1_; ++w)
                        s += xr[w] * pk[j * W_ + w];
                }
                out[(g * FG_ + f) * L_ + e] = s;
            } else {
                for (int j = 0; j < J_; ++j) {
                    const float* xr = x + rows[j] * L_;
                    for (int w = e + 1; w < W_; ++w)
                        s += xr[L_ - W_ + w] * pk[j * W_ + w];
                }
                out[(g * FG_ + f) * L_ + (L_ - PAD1_ + e)] = s;
            }
        }
    }
}

extern "C" void kernel_launch(void* const* d_in, const int* in_sizes, int n_in,
                              void* d_out, int out_size)
{
    const float* x      = (const float*)d_in[0];
    const float* params = (const float*)d_in[1];
    const int*   rel    = (const int*)d_in[2];
    float* out = (float*)d_out;

    cudaFuncSetAttribute(conv_mma, cudaFuncAttributeMaxDynamicSharedMemorySize,
                         SMEM_WORDS * 4);
    dim3 grid(L_ / KTILE_, G_);   // 512 x 8
    conv_mma<<<grid, NTH_, SMEM_WORDS * 4>>>(x, params, rel, out);
}

// round 7
// speedup vs baseline: 2.5579x; 1.1317x over previous
#include <cuda_runtime.h>
#include <cstdint>

#define G_    8
#define FG_   16
#define J_    8
#define W_    31
#define PAD1_ 15
#define L_    262144
#define KTILE_ 512
#define NTH_  256

// SMEM layout (32-bit words). yt ALIASES xs+ws (dead after main loop).
#define XS_PITCH 544                     // 512 + 31 + pad
#define XS_ELEMS (J_ * XS_PITCH)         // 4352
// ws2: [j][w0g][tig] -> 16 filter-slots of 2 words {W[f][w], W[f][w+4]}
#define WS_ELEMS (J_ * 4 * 4 * FG_ * 2)  // 4096
#define YT_PITCH 516
#define YT_ELEMS (FG_ * YT_PITCH)        // 8256
#define SM_XS 0
#define SM_WS (SM_XS + XS_ELEMS)         // 4352
#define SM_YT 0
#define SMEM_WORDS (SM_WS + WS_ELEMS)    // 8448 words = 33792 B

typedef unsigned long long ull;

__device__ __forceinline__ uint32_t cvt_tf32(float f) {
    uint32_t r;
    asm("cvt.rna.tf32.f32 %0, %1;" : "=r"(r) : "f"(f));
    return r;
}
__device__ __forceinline__ void unpack2u(ull v, uint32_t& lo, uint32_t& hi) {
    asm("mov.b64 {%0, %1}, %2;" : "=r"(lo), "=r"(hi) : "l"(v));
}

__device__ __forceinline__ void mma_tf32(float d[4],
                                         uint32_t a0, uint32_t a1,
                                         uint32_t a2, uint32_t a3,
                                         uint32_t b0, uint32_t b1) {
    asm volatile(
        "mma.sync.aligned.m16n8k8.row.col.f32.tf32.tf32.f32 "
        "{%0,%1,%2,%3}, {%4,%5,%6,%7}, {%8,%9}, {%0,%1,%2,%3};"
        : "+f"(d[0]), "+f"(d[1]), "+f"(d[2]), "+f"(d[3])
        : "r"(a0), "r"(a1), "r"(a2), "r"(a3), "r"(b0), "r"(b1));
}

// CTA: one group g, 512 consecutive k, 16 filters. Warp: 64 k x 16 f.
// A[m,kk] = xs[j][m + w0 + kk] (Toeplitz alias, no im2col duplication).
__global__ void __launch_bounds__(NTH_, 4)
conv_mma(const float* __restrict__ x,
         const float* __restrict__ params,
         const int* __restrict__ rel,
         float* __restrict__ out)
{
    extern __shared__ uint32_t sm[];
    const int tid  = threadIdx.x;
    const int wid  = tid >> 5;
    const int lane = tid & 31;
    const int gid  = lane >> 2;
    const int tig  = lane & 3;
    const int g    = blockIdx.y;
    const int tile = blockIdx.x;
    const int kb   = tile * KTILE_;

    int rows[J_];
#pragma unroll
    for (int j = 0; j < J_; ++j) rows[j] = __ldg(rel + g * J_ + j);

    // ---- stage x windows (no divides): xs[j][t] = tf32(x[row_j][clamp(kb+t-15)])
#pragma unroll 1
    for (int j = 0; j < J_; ++j) {
        const float* xr = x + rows[j] * L_;
        for (int t = tid; t < KTILE_ + W_; t += NTH_) {
            int gi = kb + t - PAD1_;
            gi = max(0, min(L_ - 1, gi));
            sm[SM_XS + j * XS_PITCH + t] = cvt_tf32(__ldg(xr + gi));
        }
    }
    // ---- stage weights as LDS.64-friendly pairs ----
    // e = j*512 + w0g*128 + tig*32 + f*2 + p ; value = W[f][w0g*8+tig+p*4]
    for (int e = tid; e < WS_ELEMS; e += NTH_) {
        int p   = e & 1;
        int f   = (e >> 1) & 15;
        int tg  = (e >> 5) & 3;
        int w0g = (e >> 7) & 3;
        int j   = e >> 9;
        int w   = w0g * 8 + tg + p * 4;
        float v = (w < W_) ? __ldg(params + ((g * FG_ + f) * J_ + j) * W_ + w) : 0.f;
        sm[SM_WS + e] = cvt_tf32(v);
    }
    __syncthreads();

    const int warpk = wid * 64;

    float acc[4][2][4];
#pragma unroll
    for (int mi = 0; mi < 4; ++mi)
#pragma unroll
        for (int nh = 0; nh < 2; ++nh)
#pragma unroll
            for (int q = 0; q < 4; ++q) acc[mi][nh][q] = 0.f;

#pragma unroll 1
    for (int j = 0; j < J_; ++j) {
        const uint32_t* xj = sm + SM_XS + j * XS_PITCH + warpk + gid + tig;

        // init A fragments for w0g = 0
        uint32_t A[4][4];
#pragma unroll
        for (int mi = 0; mi < 4; ++mi) {
            A[mi][0] = xj[mi * 16];
            A[mi][1] = xj[mi * 16 + 8];
            A[mi][2] = xj[mi * 16 + 4];
            A[mi][3] = xj[mi * 16 + 12];
        }

#pragma unroll
        for (int w0g = 0; w0g < 4; ++w0g) {
            const ull* wb = (const ull*)(sm + SM_WS + ((j * 4 + w0g) * 4 + tig) * 32) + gid;
            uint32_t b0a, b1a, b0b, b1b;
            unpack2u(wb[0], b0a, b1a);   // filter gid:   {w, w+4}
            unpack2u(wb[8], b0b, b1b);   // filter gid+8: {w, w+4}
#pragma unroll
            for (int mi = 0; mi < 4; ++mi) {
                mma_tf32(acc[mi][0], A[mi][0], A[mi][1], A[mi][2], A[mi][3], b0a, b1a);
                mma_tf32(acc[mi][1], A[mi][0], A[mi][1], A[mi][2], A[mi][3], b0b, b1b);
            }
            if (w0g < 3) {
#pragma unroll
                for (int mi = 0; mi < 4; ++mi) {
                    A[mi][0] = A[mi][1];
                    A[mi][2] = A[mi][3];
                    A[mi][1] = xj[mi * 16 + (w0g + 1) * 8 + 8];
                    A[mi][3] = xj[mi * 16 + (w0g + 1) * 8 + 12];
                }
            }
        }
    }

    __syncthreads();   // xs/ws dead; yt aliases them

    // ---- D fragments -> yt[f][k], conflict-free (pitch 516) ----
    float* yt = (float*)(sm + SM_YT);
#pragma unroll
    for (int mi = 0; mi < 4; ++mi) {
        const int k0 = warpk + mi * 16 + gid;
#pragma unroll
        for (int nh = 0; nh < 2; ++nh) {
            const int f0 = nh * 8 + 2 * tig;
            yt[f0 * YT_PITCH + k0]           = acc[mi][nh][0];
            yt[(f0 + 1) * YT_PITCH + k0]     = acc[mi][nh][1];
            yt[f0 * YT_PITCH + k0 + 8]       = acc[mi][nh][2];
            yt[(f0 + 1) * YT_PITCH + k0 + 8] = acc[mi][nh][3];
        }
    }
    __syncthreads();

    // ---- coalesced float4 store ----
    for (int i = tid; i < FG_ * (KTILE_ / 4); i += NTH_) {
        int f  = i >> 7;
        int c4 = i & 127;
        float4 v = *(const float4*)(yt + f * YT_PITCH + c4 * 4);
        *(float4*)(out + (g * FG_ + f) * L_ + kb + c4 * 4) = v;
    }

    // ---- boundary overwrite (reference truncates; no zero-pad), full fp32 ----
    if (tile == 0 || tile == (L_ / KTILE_ - 1)) {
        __syncthreads();
        if (tid < FG_ * PAD1_) {
            const int f = tid / PAD1_;
            const int e = tid % PAD1_;
            const float* pk = params + (g * FG_ + f) * (J_ * W_);
            float s = 0.f;
            if (tile == 0) {
                for (int j = 0; j < J_; ++j) {
                    const float* xr = x + __ldg(rel + g * J_ + j) * L_;
                    for (int w = 0; w <= e + PAD1_; ++w)
                        s += xr[w] * pk[j * W_ + w];
                }
                out[(g * FG_ + f) * L_ + e] = s;
            } else {
                for (int j = 0; j < J_; ++j) {
                    const float* xr = x + __ldg(rel + g * J_ + j) * L_;
                    for (int w = e + 1; w < W_; ++w)
                        s += xr[L_ - W_ + w] * pk[j * W_ + w];
                }
                out[(g * FG_ + f) * L_ + (L_ - PAD1_ + e)] = s;
            }
        }
    }
}

extern "C" void kernel_launch(void* const* d_in, const int* in_sizes, int n_in,
                              void* d_out, int out_size)
{
    const float* x      = (const float*)d_in[0];
    const float* params = (const float*)d_in[1];
    const int*   rel    = (const int*)d_in[2];
    float* out = (float*)d_out;

    cudaFuncSetAttribute(conv_mma, cudaFuncAttributeMaxDynamicSharedMemorySize,
                         SMEM_WORDS * 4);
    dim3 grid(L_ / KTILE_, G_);   // 512 x 8
    conv_mma<<<grid, NTH_, SMEM_WORDS * 4>>>(x, params, rel, out);
}

// round 8
// speedup vs baseline: 2.6033x; 1.0177x over previous
#include <cuda_runtime.h>
#include <cstdint>

#define G_    8
#define FG_   16
#define J_    8
#define W_    31
#define PAD1_ 15
#define L_    262144
#define KTILE_ 512
#define NTH_  256

// SMEM layout (32-bit words). yt ALIASES xs+ws (dead after main loop).
#define XS_PITCH 544                     // 512 + 31 + pad
#define XS_ELEMS (J_ * XS_PITCH)         // 4352
// ws2: [j][w0g][tig] -> 16 filter-slots of 2 words {W[f][w], W[f][w+4]}
#define WS_ELEMS (J_ * 4 * 4 * FG_ * 2)  // 4096
#define YT_PITCH 516
#define YT_ELEMS (FG_ * YT_PITCH)        // 8256
#define SM_XS 0
#define SM_WS (SM_XS + XS_ELEMS)         // 4352
#define SM_YT 0
#define SMEM_WORDS (SM_WS + WS_ELEMS)    // 8448 words = 33792 B

typedef unsigned long long ull;

__device__ __forceinline__ uint32_t cvt_tf32(float f) {
    uint32_t r;
    asm("cvt.rna.tf32.f32 %0, %1;" : "=r"(r) : "f"(f));
    return r;
}
__device__ __forceinline__ void unpack2u(ull v, uint32_t& lo, uint32_t& hi) {
    asm("mov.b64 {%0, %1}, %2;" : "=r"(lo), "=r"(hi) : "l"(v));
}

__device__ __forceinline__ void mma_tf32(float d[4],
                                         uint32_t a0, uint32_t a1,
                                         uint32_t a2, uint32_t a3,
                                         uint32_t b0, uint32_t b1) {
    asm volatile(
        "mma.sync.aligned.m16n8k8.row.col.f32.tf32.tf32.f32 "
        "{%0,%1,%2,%3}, {%4,%5,%6,%7}, {%8,%9}, {%0,%1,%2,%3};"
        : "+f"(d[0]), "+f"(d[1]), "+f"(d[2]), "+f"(d[3])
        : "r"(a0), "r"(a1), "r"(a2), "r"(a3), "r"(b0), "r"(b1));
}

// CTA: one group g, 512 consecutive k, 16 filters. Warp: 64 k x 16 f.
// A[m,kk] = xs[j][m + w0 + kk] (Toeplitz alias). All A values a warp needs
// for one j are xj[4*i], i=0..21 -> load once into X[22], fragments indexed
// from registers: zero redundant LDS.
__global__ void __launch_bounds__(NTH_, 4)
conv_mma(const float* __restrict__ x,
         const float* __restrict__ params,
         const int* __restrict__ rel,
         float* __restrict__ out)
{
    extern __shared__ uint32_t sm[];
    const int tid  = threadIdx.x;
    const int wid  = tid >> 5;
    const int lane = tid & 31;
    const int gid  = lane >> 2;
    const int tig  = lane & 3;
    const int g    = blockIdx.y;
    const int tile = blockIdx.x;
    const int kb   = tile * KTILE_;

    int rows[J_];
#pragma unroll
    for (int j = 0; j < J_; ++j) rows[j] = __ldg(rel + g * J_ + j);

    // ---- stage x windows: xs[j][t] = tf32(x[row_j][clamp(kb+t-15)]) ----
#pragma unroll 1
    for (int j = 0; j < J_; ++j) {
        const float* xr = x + rows[j] * L_;
        for (int t = tid; t < KTILE_ + W_; t += NTH_) {
            int gi = kb + t - PAD1_;
            gi = max(0, min(L_ - 1, gi));
            sm[SM_XS + j * XS_PITCH + t] = cvt_tf32(__ldg(xr + gi));
        }
    }
    // ---- stage weights as LDS.64-friendly pairs ----
    // e = j*512 + w0g*128 + tig*32 + f*2 + p ; value = W[f][w0g*8+tig+p*4]
    for (int e = tid; e < WS_ELEMS; e += NTH_) {
        int p   = e & 1;
        int f   = (e >> 1) & 15;
        int tg  = (e >> 5) & 3;
        int w0g = (e >> 7) & 3;
        int j   = e >> 9;
        int w   = w0g * 8 + tg + p * 4;
        float v = (w < W_) ? __ldg(params + ((g * FG_ + f) * J_ + j) * W_ + w) : 0.f;
        sm[SM_WS + e] = cvt_tf32(v);
    }
    __syncthreads();

    const int warpk = wid * 64;

    float acc[4][2][4];
#pragma unroll
    for (int mi = 0; mi < 4; ++mi)
#pragma unroll
        for (int nh = 0; nh < 2; ++nh)
#pragma unroll
            for (int q = 0; q < 4; ++q) acc[mi][nh][q] = 0.f;

#pragma unroll 1
    for (int j = 0; j < J_; ++j) {
        const uint32_t* xj = sm + SM_XS + j * XS_PITCH + warpk + gid + tig;

        // register window: X[i] = xj[4i] covers all fragments of this j
        uint32_t X[22];
#pragma unroll
        for (int i = 0; i < 22; ++i) X[i] = xj[4 * i];

#pragma unroll
        for (int w0g = 0; w0g < 4; ++w0g) {
            const ull* wb = (const ull*)(sm + SM_WS + ((j * 4 + w0g) * 4 + tig) * 32) + gid;
            uint32_t b0a, b1a, b0b, b1b;
            unpack2u(wb[0], b0a, b1a);   // filter gid:   {w, w+4}
            unpack2u(wb[8], b0b, b1b);   // filter gid+8: {w, w+4}
#pragma unroll
            for (int mi = 0; mi < 4; ++mi) {
                const int i0 = 4 * mi + 2 * w0g;
                mma_tf32(acc[mi][0], X[i0], X[i0 + 2], X[i0 + 1], X[i0 + 3], b0a, b1a);
                mma_tf32(acc[mi][1], X[i0], X[i0 + 2], X[i0 + 1], X[i0 + 3], b0b, b1b);
            }
        }
    }

    __syncthreads();   // xs/ws dead; yt aliases them

    // ---- D fragments -> yt[f][k], conflict-free (pitch 516) ----
    float* yt = (float*)(sm + SM_YT);
#pragma unroll
    for (int mi = 0; mi < 4; ++mi) {
        const int k0 = warpk + mi * 16 + gid;
#pragma unroll
        for (int nh = 0; nh < 2; ++nh) {
            const int f0 = nh * 8 + 2 * tig;
            yt[f0 * YT_PITCH + k0]           = acc[mi][nh][0];
            yt[(f0 + 1) * YT_PITCH + k0]     = acc[mi][nh][1];
            yt[f0 * YT_PITCH + k0 + 8]       = acc[mi][nh][2];
            yt[(f0 + 1) * YT_PITCH + k0 + 8] = acc[mi][nh][3];
        }
    }
    __syncthreads();

    // ---- coalesced float4 store ----
    for (int i = tid; i < FG_ * (KTILE_ / 4); i += NTH_) {
        int f  = i >> 7;
        int c4 = i & 127;
        float4 v = *(const float4*)(yt + f * YT_PITCH + c4 * 4);
        *(float4*)(out + (g * FG_ + f) * L_ + kb + c4 * 4) = v;
    }

    // ---- boundary overwrite (reference truncates; no zero-pad), full fp32 ----
    if (tile == 0 || tile == (L_ / KTILE_ - 1)) {
        __syncthreads();
        if (tid < FG_ * PAD1_) {
            const int f = tid / PAD1_;
            const int e = tid % PAD1_;
            const float* pk = params + (g * FG_ + f) * (J_ * W_);
            float s = 0.f;
            if (tile == 0) {
                for (int j = 0; j < J_; ++j) {
                    const float* xr = x + __ldg(rel + g * J_ + j) * L_;
                    for (int w = 0; w <= e + PAD1_; ++w)
                        s += xr[w] * pk[j * W_ + w];
                }
                out[(g * FG_ + f) * L_ + e] = s;
            } else {
                for (int j = 0; j < J_; ++j) {
                    const float* xr = x + __ldg(rel + g * J_ + j) * L_;
                    for (int w = e + 1; w < W_; ++w)
                        s += xr[L_ - W_ + w] * pk[j * W_ + w];
                }
                out[(g * FG_ + f) * L_ + (L_ - PAD1_ + e)] = s;
            }
        }
    }
}

extern "C" void kernel_launch(void* const* d_in, const int* in_sizes, int n_in,
                              void* d_out, int out_size)
{
    const float* x      = (const float*)d_in[0];
    const float* params = (const float*)d_in[1];
    const int*   rel    = (const int*)d_in[2];
    float* out = (float*)d_out;

    cudaFuncSetAttribute(conv_mma, cudaFuncAttributeMaxDynamicSharedMemorySize,
                         SMEM_WORDS * 4);
    dim3 grid(L_ / KTILE_, G_);   // 512 x 8
    conv_mma<<<grid, NTH_, SMEM_WORDS * 4>>>(x, params, rel, out);
}

// round 9
// speedup vs baseline: 2.9317x; 1.1261x over previous
#include <cuda_runtime.h>
#include <cstdint>

#define G_    8
#define FG_   16
#define J_    8
#define W_    31
#define PAD1_ 15
#define L_    262144
#define KTILE_ 512
#define NTH_  256

// SMEM layout (32-bit words). yt ALIASES xs+ws (dead after main loop).
#define XS_PITCH 544                     // 512 + 31 + pad
#define XS_ELEMS (J_ * XS_PITCH)         // 4352
// ws3: [j][w0g][fhi][lane] -> ull slot per lane (coalesced LDS.64)
#define WS_ELEMS (J_ * 4 * 2 * 32 * 2)   // 4096 words
#define YT_PITCH 516
#define YT_ELEMS (FG_ * YT_PITCH)        // 8256
#define SM_XS 0
#define SM_WS (SM_XS + XS_ELEMS)         // 4352
#define SM_YT 0
#define SMEM_WORDS (SM_WS + WS_ELEMS)    // 8448 words = 33792 B

typedef unsigned long long ull;

__device__ __forceinline__ uint32_t cvt_tf32(float f) {
    uint32_t r;
    asm("cvt.rna.tf32.f32 %0, %1;" : "=r"(r) : "f"(f));
    return r;
}
__device__ __forceinline__ void unpack2u(ull v, uint32_t& lo, uint32_t& hi) {
    asm("mov.b64 {%0, %1}, %2;" : "=r"(lo), "=r"(hi) : "l"(v));
}

__device__ __forceinline__ void mma_tf32(float d[4],
                                         uint32_t a0, uint32_t a1,
                                         uint32_t a2, uint32_t a3,
                                         uint32_t b0, uint32_t b1) {
    asm volatile(
        "mma.sync.aligned.m16n8k8.row.col.f32.tf32.tf32.f32 "
        "{%0,%1,%2,%3}, {%4,%5,%6,%7}, {%8,%9}, {%0,%1,%2,%3};"
        : "+f"(d[0]), "+f"(d[1]), "+f"(d[2]), "+f"(d[3])
        : "r"(a0), "r"(a1), "r"(a2), "r"(a3), "r"(b0), "r"(b1));
}

// CTA: one group g, 512 consecutive k, 16 filters. Warp: 64 k x 16 f.
// A[m,kk] = xs[j][m + w0 + kk] (Toeplitz alias; X[22] register window).
// B: per (j,w0g,fhi) the warp reads ull slots 0..31 in lane order —
// canonical coalesced LDS.64, zero bank conflicts.
__global__ void __launch_bounds__(NTH_, 4)
conv_mma(const float* __restrict__ x,
         const float* __restrict__ params,
         const int* __restrict__ rel,
         float* __restrict__ out)
{
    extern __shared__ uint32_t sm[];
    const int tid  = threadIdx.x;
    const int wid  = tid >> 5;
    const int lane = tid & 31;
    const int gid  = lane >> 2;
    const int tig  = lane & 3;
    const int g    = blockIdx.y;
    const int tile = blockIdx.x;
    const int kb   = tile * KTILE_;

    int rows[J_];
#pragma unroll
    for (int j = 0; j < J_; ++j) rows[j] = __ldg(rel + g * J_ + j);

    // ---- stage x windows: xs[j][t] = tf32(x[row_j][clamp(kb+t-15)]) ----
#pragma unroll 1
    for (int j = 0; j < J_; ++j) {
        const float* xr = x + rows[j] * L_;
        for (int t = tid; t < KTILE_ + W_; t += NTH_) {
            int gi = kb + t - PAD1_;
            gi = max(0, min(L_ - 1, gi));
            sm[SM_XS + j * XS_PITCH + t] = cvt_tf32(__ldg(xr + gi));
        }
    }
    // ---- stage weights, lane-ordered ull slots ----
    // word e = j*512 + w0g*128 + fhi*64 + ln*2 + p
    // value  = W[fhi*8 + (ln>>2)][w0g*8 + (ln&3) + p*4]   (zero-pad w=31)
    for (int e = tid; e < WS_ELEMS; e += NTH_) {
        int p   = e & 1;
        int ln  = (e >> 1) & 31;
        int fhi = (e >> 6) & 1;
        int w0g = (e >> 7) & 3;
        int j   = e >> 9;
        int f   = fhi * 8 + (ln >> 2);
        int w   = w0g * 8 + (ln & 3) + p * 4;
        float v = (w < W_) ? __ldg(params + ((g * FG_ + f) * J_ + j) * W_ + w) : 0.f;
        sm[SM_WS + e] = cvt_tf32(v);
    }
    __syncthreads();

    const int warpk = wid * 64;

    float acc[4][2][4];
#pragma unroll
    for (int mi = 0; mi < 4; ++mi)
#pragma unroll
        for (int nh = 0; nh < 2; ++nh)
#pragma unroll
            for (int q = 0; q < 4; ++q) acc[mi][nh][q] = 0.f;

#pragma unroll 1
    for (int j = 0; j < J_; ++j) {
        const uint32_t* xj = sm + SM_XS + j * XS_PITCH + warpk + gid + tig;
        const ull* wj = (const ull*)(sm + SM_WS + j * 512) + lane;

        // register window: X[i] = xj[4i] covers all fragments of this j
        uint32_t X[22];
#pragma unroll
        for (int i = 0; i < 22; ++i) X[i] = xj[4 * i];

#pragma unroll
        for (int w0g = 0; w0g < 4; ++w0g) {
            uint32_t b0a, b1a, b0b, b1b;
            unpack2u(wj[w0g * 64], b0a, b1a);        // fhi=0: filter gid
            unpack2u(wj[w0g * 64 + 32], b0b, b1b);   // fhi=1: filter gid+8
#pragma unroll
            for (int mi = 0; mi < 4; ++mi) {
                const int i0 = 4 * mi + 2 * w0g;
                mma_tf32(acc[mi][0], X[i0], X[i0 + 2], X[i0 + 1], X[i0 + 3], b0a, b1a);
                mma_tf32(acc[mi][1], X[i0], X[i0 + 2], X[i0 + 1], X[i0 + 3], b0b, b1b);
            }
        }
    }

    __syncthreads();   // xs/ws dead; yt aliases them

    // ---- D fragments -> yt[f][k], conflict-free (pitch 516) ----
    float* yt = (float*)(sm + SM_YT);
#pragma unroll
    for (int mi = 0; mi < 4; ++mi) {
        const int k0 = warpk + mi * 16 + gid;
#pragma unroll
        for (int nh = 0; nh < 2; ++nh) {
            const int f0 = nh * 8 + 2 * tig;
            yt[f0 * YT_PITCH + k0]           = acc[mi][nh][0];
            yt[(f0 + 1) * YT_PITCH + k0]     = acc[mi][nh][1];
            yt[f0 * YT_PITCH + k0 + 8]       = acc[mi][nh][2];
            yt[(f0 + 1) * YT_PITCH + k0 + 8] = acc[mi][nh][3];
        }
    }
    __syncthreads();

    // ---- coalesced float4 store ----
    for (int i = tid; i < FG_ * (KTILE_ / 4); i += NTH_) {
        int f  = i >> 7;
        int c4 = i & 127;
        float4 v = *(const float4*)(yt + f * YT_PITCH + c4 * 4);
        *(float4*)(out + (g * FG_ + f) * L_ + kb + c4 * 4) = v;
    }

    // ---- boundary overwrite (reference truncates; no zero-pad), full fp32 ----
    if (tile == 0 || tile == (L_ / KTILE_ - 1)) {
        __syncthreads();
        if (tid < FG_ * PAD1_) {
            const int f = tid / PAD1_;
            const int e = tid % PAD1_;
            const float* pk = params + (g * FG_ + f) * (J_ * W_);
            float s = 0.f;
            if (tile == 0) {
                for (int j = 0; j < J_; ++j) {
                    const float* xr = x + __ldg(rel + g * J_ + j) * L_;
                    for (int w = 0; w <= e + PAD1_; ++w)
                        s += xr[w] * pk[j * W_ + w];
                }
                out[(g * FG_ + f) * L_ + e] = s;
            } else {
                for (int j = 0; j < J_; ++j) {
                    const float* xr = x + __ldg(rel + g * J_ + j) * L_;
                    for (int w = e + 1; w < W_; ++w)
                        s += xr[L_ - W_ + w] * pk[j * W_ + w];
                }
                out[(g * FG_ + f) * L_ + (L_ - PAD1_ + e)] = s;
            }
        }
    }
}

extern "C" void kernel_launch(void* const* d_in, const int* in_sizes, int n_in,
                              void* d_out, int out_size)
{
    const float* x      = (const float*)d_in[0];
    const float* params = (const float*)d_in[1];
    const int*   rel    = (const int*)d_in[2];
    float* out = (float*)d_out;

    cudaFuncSetAttribute(conv_mma, cudaFuncAttributeMaxDynamicSharedMemorySize,
                         SMEM_WORDS * 4);
    dim3 grid(L_ / KTILE_, G_);   // 512 x 8
    conv_mma<<<grid, NTH_, SMEM_WORDS * 4>>>(x, params, rel, out);
}

// round 10
// speedup vs baseline: 4.1338x; 1.4100x over previous
#include <cuda_runtime.h>
#include <cstdint>

#define G_    8
#define FG_   16
#define J_    8
#define W_    31
#define PAD1_ 15
#define L_    262144
#define KTILE_ 512
#define NTH_  256

// SMEM layout (32-bit words). yt ALIASES xs+ws (dead after main loop).
// xs shifted: xs[j][s] = x[kb + s - 16], s in [0,544); consumers read +1.
#define XS_PITCH 548
#define XS_ELEMS (J_ * XS_PITCH)         // 4384
// ws4: [j][w0g][lane] -> uint4 {W[gid][w],W[gid][w+4],W[gid+8][w],W[gid+8][w+4]}
#define WS_ELEMS (J_ * 4 * 32 * 4)       // 4096 words
#define YT_PITCH 516
#define YT_ELEMS (FG_ * YT_PITCH)        // 8256
#define SM_XS 0
#define SM_WS (SM_XS + XS_ELEMS)         // 4384
#define SM_YT 0
#define SMEM_WORDS (SM_WS + WS_ELEMS)    // 8480 words = 33920 B

__device__ __forceinline__ uint32_t cvt_tf32(float f) {
    uint32_t r;
    asm("cvt.rna.tf32.f32 %0, %1;" : "=r"(r) : "f"(f));
    return r;
}

__device__ __forceinline__ void mma_tf32(float d[4],
                                         uint32_t a0, uint32_t a1,
                                         uint32_t a2, uint32_t a3,
                                         uint32_t b0, uint32_t b1) {
    asm volatile(
        "mma.sync.aligned.m16n8k8.row.col.f32.tf32.tf32.f32 "
        "{%0,%1,%2,%3}, {%4,%5,%6,%7}, {%8,%9}, {%0,%1,%2,%3};"
        : "+f"(d[0]), "+f"(d[1]), "+f"(d[2]), "+f"(d[3])
        : "r"(a0), "r"(a1), "r"(a2), "r"(a3), "r"(b0), "r"(b1));
}

// CTA: one group g, 512 consecutive k, 16 filters. Warp: 64 k x 16 f.
// A[m,kk] = xs[j][m + w0 + kk] (Toeplitz alias; X[22] register window).
// B: one coalesced LDS.128 per (j,w0g), double-buffered across w0g.
__global__ void __launch_bounds__(NTH_, 4)
conv_mma(const float* __restrict__ x,
         const float* __restrict__ params,
         const int* __restrict__ rel,
         float* __restrict__ out)
{
    extern __shared__ uint32_t sm[];
    const int tid  = threadIdx.x;
    const int wid  = tid >> 5;
    const int lane = tid & 31;
    const int gid  = lane >> 2;
    const int tig  = lane & 3;
    const int g    = blockIdx.y;
    const int tile = blockIdx.x;
    const int kb   = tile * KTILE_;
    const int last = L_ / KTILE_ - 1;

    int rows[J_];
#pragma unroll
    for (int j = 0; j < J_; ++j) rows[j] = __ldg(rel + g * J_ + j);

    // ---- stage x windows: xs[j][s] = tf32(x[kb + s - 16]) ----
    if (tile != 0 && tile != last) {
        // interior: aligned LDG.128 + STS.128, no clamping
#pragma unroll 1
        for (int j = 0; j < J_; ++j) {
            const float4* xp = (const float4*)(x + rows[j] * L_ + kb - 16);
            uint32_t* xd = sm + SM_XS + j * XS_PITCH;
            for (int q = tid; q < 136; q += NTH_) {
                float4 v = __ldg(xp + q);
                uint4 o;
                o.x = cvt_tf32(v.x); o.y = cvt_tf32(v.y);
                o.z = cvt_tf32(v.z); o.w = cvt_tf32(v.w);
                *(uint4*)(xd + 4 * q) = o;
            }
        }
    } else {
        // edge tiles: clamped scalar path (pollutes only overwritten outputs)
#pragma unroll 1
        for (int j = 0; j < J_; ++j) {
            const float* xr = x + rows[j] * L_;
            for (int s = tid; s < 544; s += NTH_) {
                int gi = kb + s - 16;
                gi = max(0, min(L_ - 1, gi));
                sm[SM_XS + j * XS_PITCH + s] = cvt_tf32(__ldg(xr + gi));
            }
        }
    }
    // ---- stage weights as uint4 slots, lane-ordered ----
    // uint4 e: ln = e&31, w0g = (e>>5)&3, j = e>>7 ; w = w0g*8 + (ln&3)
    for (int e = tid; e < J_ * 4 * 32; e += NTH_) {
        int ln  = e & 31;
        int w0g = (e >> 5) & 3;
        int j   = e >> 7;
        int w   = w0g * 8 + (ln & 3);
        int flo = ln >> 2;
        const float* pw = params + ((g * FG_ + flo) * J_ + j) * W_;
        bool hasw4 = (w + 4 < W_);
        uint4 o;
        o.x = cvt_tf32(__ldg(pw + w));
        o.y = hasw4 ? cvt_tf32(__ldg(pw + w + 4)) : 0u;
        o.z = cvt_tf32(__ldg(pw + 8 * (J_ * W_) + w));
        o.w = hasw4 ? cvt_tf32(__ldg(pw + 8 * (J_ * W_) + w + 4)) : 0u;
        *(uint4*)(sm + SM_WS + e * 4) = o;
    }
    __syncthreads();

    const int warpk = wid * 64;

    float acc[4][2][4];
#pragma unroll
    for (int mi = 0; mi < 4; ++mi)
#pragma unroll
        for (int nh = 0; nh < 2; ++nh)
#pragma unroll
            for (int q = 0; q < 4; ++q) acc[mi][nh][q] = 0.f;

#pragma unroll 1
    for (int j = 0; j < J_; ++j) {
        const uint32_t* xj = sm + SM_XS + j * XS_PITCH + 1 + warpk + gid + tig;
        const uint4* wj = (const uint4*)(sm + SM_WS + j * 512) + lane;

        // register window: X[i] = xj[4i] covers all fragments of this j
        uint32_t X[22];
#pragma unroll
        for (int i = 0; i < 22; ++i) X[i] = xj[4 * i];

        uint4 B = wj[0];
#pragma unroll
        for (int w0g = 0; w0g < 4; ++w0g) {
            uint4 Bn = wj[(w0g < 3 ? w0g + 1 : 3) * 32];   // prefetch next
#pragma unroll
            for (int mi = 0; mi < 4; ++mi) {
                const int i0 = 4 * mi + 2 * w0g;
                mma_tf32(acc[mi][0], X[i0], X[i0 + 2], X[i0 + 1], X[i0 + 3], B.x, B.y);
                mma_tf32(acc[mi][1], X[i0], X[i0 + 2], X[i0 + 1], X[i0 + 3], B.z, B.w);
            }
            B = Bn;
        }
    }

    __syncthreads();   // xs/ws dead; yt aliases them

    // ---- D fragments -> yt[f][k], conflict-free (pitch 516) ----
    float* yt = (float*)(sm + SM_YT);
#pragma unroll
    for (int mi = 0; mi < 4; ++mi) {
        const int k0 = warpk + mi * 16 + gid;
#pragma unroll
        for (int nh = 0; nh < 2; ++nh) {
            const int f0 = nh * 8 + 2 * tig;
            yt[f0 * YT_PITCH + k0]           = acc[mi][nh][0];
            yt[(f0 + 1) * YT_PITCH + k0]     = acc[mi][nh][1];
            yt[f0 * YT_PITCH + k0 + 8]       = acc[mi][nh][2];
            yt[(f0 + 1) * YT_PITCH + k0 + 8] = acc[mi][nh][3];
        }
    }
    __syncthreads();

    // ---- coalesced float4 store ----
    for (int i = tid; i < FG_ * (KTILE_ / 4); i += NTH_) {
        int f  = i >> 7;
        int c4 = i & 127;
        float4 v = *(const float4*)(yt + f * YT_PITCH + c4 * 4);
        *(float4*)(out + (g * FG_ + f) * L_ + kb + c4 * 4) = v;
    }

    // ---- boundary overwrite (reference truncates; no zero-pad), full fp32 ----
    if (tile == 0 || tile == last) {
        __syncthreads();
        if (tid < FG_ * PAD1_) {
            const int f = tid / PAD1_;
            const int e = tid % PAD1_;
            const float* pk = params + (g * FG_ + f) * (J_ * W_);
            float s = 0.f;
            if (tile == 0) {
                for (int j = 0; j < J_; ++j) {
                    const float* xr = x + __ldg(rel + g * J_ + j) * L_;
                    for (int w = 0; w <= e + PAD1_; ++w)
                        s += xr[w] * pk[j * W_ + w];
                }
                out[(g * FG_ + f) * L_ + e] = s;
            } else {
                for (int j = 0; j < J_; ++j) {
                    const float* xr = x + __ldg(rel + g * J_ + j) * L_;
                    for (int w = e + 1; w < W_; ++w)
                        s += xr[L_ - W_ + w] * pk[j * W_ + w];
                }
                out[(g * FG_ + f) * L_ + (L_ - PAD1_ + e)] = s;
            }
        }
    }
}

extern "C" void kernel_launch(void* const* d_in, const int* in_sizes, int n_in,
                              void* d_out, int out_size)
{
    const float* x      = (const float*)d_in[0];
    const float* params = (const float*)d_in[1];
    const int*   rel    = (const int*)d_in[2];
    float* out = (float*)d_out;

    cudaFuncSetAttribute(conv_mma, cudaFuncAttributeMaxDynamicSharedMemorySize,
                         SMEM_WORDS * 4);
    dim3 grid(L_ / KTILE_, G_);   // 512 x 8
    conv_mma<<<grid, NTH_, SMEM_WORDS * 4>>>(x, params, rel, out);
}

// round 11
// speedup vs baseline: 4.3903x; 1.0620x over previous
#include <cuda_runtime.h>
#include <cstdint>

#define G_    8
#define FG_   16
#define J_    8
#define W_    31
#define PAD1_ 15
#define L_    262144
#define KTILE_ 512
#define NTH_  256

// SMEM layout (32-bit words). yt ALIASES xs+ws (dead after main loop).
// xs shifted: xs[j][s] = x[kb + s - 16], s in [0,544); consumers read +1.
#define XS_PITCH 548                     // 548*4 = 2192 B, 16B-aligned pitch
#define XS_ELEMS (J_ * XS_PITCH)         // 4384
// ws4: [j][w0g][lane] -> uint4 {W[gid][w],W[gid][w+4],W[gid+8][w],W[gid+8][w+4]}
#define WS_ELEMS (J_ * 4 * 32 * 4)       // 4096 words
#define YT_PITCH 516
#define YT_ELEMS (FG_ * YT_PITCH)        // 8256
#define SM_XS 0
#define SM_WS (SM_XS + XS_ELEMS)         // 4384
#define SM_YT 0
#define SMEM_WORDS (SM_WS + WS_ELEMS)    // 8480 words = 33920 B

__device__ __forceinline__ uint32_t cvt_tf32(float f) {
    uint32_t r;
    asm("cvt.rna.tf32.f32 %0, %1;" : "=r"(r) : "f"(f));
    return r;
}

// 16B async copy, L1-bypass (.cg): global -> shared, no RF round trip.
__device__ __forceinline__ void cp16(uint32_t dst_smem, const void* src) {
    asm volatile("cp.async.cg.shared.global [%0], [%1], 16;"
                 :: "r"(dst_smem), "l"(src) : "memory");
}

__device__ __forceinline__ void mma_tf32(float d[4],
                                         uint32_t a0, uint32_t a1,
                                         uint32_t a2, uint32_t a3,
                                         uint32_t b0, uint32_t b1) {
    asm volatile(
        "mma.sync.aligned.m16n8k8.row.col.f32.tf32.tf32.f32 "
        "{%0,%1,%2,%3}, {%4,%5,%6,%7}, {%8,%9}, {%0,%1,%2,%3};"
        : "+f"(d[0]), "+f"(d[1]), "+f"(d[2]), "+f"(d[3])
        : "r"(a0), "r"(a1), "r"(a2), "r"(a3), "r"(b0), "r"(b1));
}

// CTA: one group g, 512 consecutive k, 16 filters. Warp: 64 k x 16 f.
// A[m,kk] = xs[j][m + w0 + kk] (Toeplitz alias; X[22] register window).
// x staged RAW via cp.async (tf32 = HW truncation of fp32 operand bits);
// weights staged with cvt.rna. B: one coalesced LDS.128 per (j,w0g),
// double-buffered across w0g.
__global__ void __launch_bounds__(NTH_, 4)
conv_mma(const float* __restrict__ x,
         const float* __restrict__ params,
         const int* __restrict__ rel,
         float* __restrict__ out)
{
    extern __shared__ uint32_t sm[];
    const uint32_t smb = (uint32_t)__cvta_generic_to_shared(sm);
    const int tid  = threadIdx.x;
    const int wid  = tid >> 5;
    const int lane = tid & 31;
    const int gid  = lane >> 2;
    const int tig  = lane & 3;
    const int g    = blockIdx.y;
    const int tile = blockIdx.x;
    const int kb   = tile * KTILE_;
    const int last = L_ / KTILE_ - 1;

    int rows[J_];
#pragma unroll
    for (int j = 0; j < J_; ++j) rows[j] = __ldg(rel + g * J_ + j);

    // ---- stage x windows: xs[j][s] = bits(x[kb + s - 16]) ----
    if (tile != 0 && tile != last) {
        // interior: pure cp.async, 1 instr / 16B, no cvt, no RF traffic
#pragma unroll 1
        for (int j = 0; j < J_; ++j) {
            const char* xp = (const char*)(x + rows[j] * L_ + kb - 16);
            uint32_t xd = smb + (SM_XS + j * XS_PITCH) * 4;
            for (int q = tid; q < 136; q += NTH_)
                cp16(xd + 16 * q, xp + 16 * q);
        }
        asm volatile("cp.async.commit_group;" ::: "memory");
    } else {
        // edge tiles: clamped scalar path (pollutes only overwritten outputs)
#pragma unroll 1
        for (int j = 0; j < J_; ++j) {
            const float* xr = x + rows[j] * L_;
            for (int s = tid; s < 544; s += NTH_) {
                int gi = kb + s - 16;
                gi = max(0, min(L_ - 1, gi));
                sm[SM_XS + j * XS_PITCH + s] = __float_as_uint(__ldg(xr + gi));
            }
        }
    }
    // ---- stage weights as uint4 slots, lane-ordered (rna-rounded) ----
    for (int e = tid; e < J_ * 4 * 32; e += NTH_) {
        int ln  = e & 31;
        int w0g = (e >> 5) & 3;
        int j   = e >> 7;
        int w   = w0g * 8 + (ln & 3);
        int flo = ln >> 2;
        const float* pw = params + ((g * FG_ + flo) * J_ + j) * W_;
        bool hasw4 = (w + 4 < W_);
        uint4 o;
        o.x = cvt_tf32(__ldg(pw + w));
        o.y = hasw4 ? cvt_tf32(__ldg(pw + w + 4)) : 0u;
        o.z = cvt_tf32(__ldg(pw + 8 * (J_ * W_) + w));
        o.w = hasw4 ? cvt_tf32(__ldg(pw + 8 * (J_ * W_) + w + 4)) : 0u;
        *(uint4*)(sm + SM_WS + e * 4) = o;
    }
    if (tile != 0 && tile != last)
        asm volatile("cp.async.wait_group 0;" ::: "memory");
    __syncthreads();

    const int warpk = wid * 64;

    float acc[4][2][4];
#pragma unroll
    for (int mi = 0; mi < 4; ++mi)
#pragma unroll
        for (int nh = 0; nh < 2; ++nh)
#pragma unroll
            for (int q = 0; q < 4; ++q) acc[mi][nh][q] = 0.f;

#pragma unroll 1
    for (int j = 0; j < J_; ++j) {
        const uint32_t* xj = sm + SM_XS + j * XS_PITCH + 1 + warpk + gid + tig;
        const uint4* wj = (const uint4*)(sm + SM_WS + j * 512) + lane;

        // register window: X[i] = xj[4i] covers all fragments of this j
        uint32_t X[22];
#pragma unroll
        for (int i = 0; i < 22; ++i) X[i] = xj[4 * i];

        uint4 B = wj[0];
#pragma unroll
        for (int w0g = 0; w0g < 4; ++w0g) {
            uint4 Bn = wj[(w0g < 3 ? w0g + 1 : 3) * 32];   // prefetch next
#pragma unroll
            for (int mi = 0; mi < 4; ++mi) {
                const int i0 = 4 * mi + 2 * w0g;
                mma_tf32(acc[mi][0], X[i0], X[i0 + 2], X[i0 + 1], X[i0 + 3], B.x, B.y);
                mma_tf32(acc[mi][1], X[i0], X[i0 + 2], X[i0 + 1], X[i0 + 3], B.z, B.w);
            }
            B = Bn;
        }
    }

    __syncthreads();   // xs/ws dead; yt aliases them

    // ---- D fragments -> yt[f][k], conflict-free (pitch 516) ----
    float* yt = (float*)(sm + SM_YT);
#pragma unroll
    for (int mi = 0; mi < 4; ++mi) {
        const int k0 = warpk + mi * 16 + gid;
#pragma unroll
        for (int nh = 0; nh < 2; ++nh) {
            const int f0 = nh * 8 + 2 * tig;
            yt[f0 * YT_PITCH + k0]           = acc[mi][nh][0];
            yt[(f0 + 1) * YT_PITCH + k0]     = acc[mi][nh][1];
            yt[f0 * YT_PITCH + k0 + 8]       = acc[mi][nh][2];
            yt[(f0 + 1) * YT_PITCH + k0 + 8] = acc[mi][nh][3];
        }
    }
    __syncthreads();

    // ---- coalesced float4 store ----
    for (int i = tid; i < FG_ * (KTILE_ / 4); i += NTH_) {
        int f  = i >> 7;
        int c4 = i & 127;
        float4 v = *(const float4*)(yt + f * YT_PITCH + c4 * 4);
        *(float4*)(out + (g * FG_ + f) * L_ + kb + c4 * 4) = v;
    }

    // ---- boundary overwrite (reference truncates; no zero-pad), full fp32 ----
    if (tile == 0 || tile == last) {
        __syncthreads();
        if (tid < FG_ * PAD1_) {
            const int f = tid / PAD1_;
            const int e = tid % PAD1_;
            const float* pk = params + (g * FG_ + f) * (J_ * W_);
            float s = 0.f;
            if (tile == 0) {
                for (int j = 0; j < J_; ++j) {
                    const float* xr = x + __ldg(rel + g * J_ + j) * L_;
                    for (int w = 0; w <= e + PAD1_; ++w)
                        s += xr[w] * pk[j * W_ + w];
                }
                out[(g * FG_ + f) * L_ + e] = s;
            } else {
                for (int j = 0; j < J_; ++j) {
                    const float* xr = x + __ldg(rel + g * J_ + j) * L_;
                    for (int w = e + 1; w < W_; ++w)
                        s += xr[L_ - W_ + w] * pk[j * W_ + w];
                }
                out[(g * FG_ + f) * L_ + (L_ - PAD1_ + e)] = s;
            }
        }
    }
}

extern "C" void kernel_launch(void* const* d_in, const int* in_sizes, int n_in,
                              void* d_out, int out_size)
{
    const float* x      = (const float*)d_in[0];
    const float* params = (const float*)d_in[1];
    const int*   rel    = (const int*)d_in[2];
    float* out = (float*)d_out;

    cudaFuncSetAttribute(conv_mma, cudaFuncAttributeMaxDynamicSharedMemorySize,
                         SMEM_WORDS * 4);
    dim3 grid(L_ / KTILE_, G_);   // 512 x 8
    conv_mma<<<grid, NTH_, SMEM_WORDS * 4>>>(x, params, rel, out);
}